// round 14
// baseline (speedup 1.0000x reference)
#include <cuda_runtime.h>
#include <cuda_fp16.h>
#include <stdint.h>
#include <math.h>

// ---------------------------------------------------------------------------
// EMLLA block, fp16. R11/R13 GEMMs (mma.sync f16-acc, persistent
// weight-resident; ~69 TF/s = mma.sync ceiling on this target). This round:
// glue-only — kv split 8, att grid 28, dwconv/lepe 4x2 pixel tiles.
// ---------------------------------------------------------------------------

constexpr int Himg = 56, Wimg = 56, Lseq = 3136, Cdim = 192;
constexpr int NHEAD = 6, HDIM = 32, BATCH = 16;
constexpr int BL = BATCH * Lseq;
constexpr float LN_EPS = 1e-5f;
constexpr int GK = 192;
constexpr int KVSPLIT = 8;

// Scratch (device globals: allocation-free, graph-capture safe)
__device__ __align__(16) __half g_xnh [(size_t)BL * Cdim];
__device__ __align__(16) __half g_h0h [(size_t)BL * Cdim];
__device__ __align__(16) __half g_acth[(size_t)BL * Cdim];
__device__ __align__(16) __half g_hh  [(size_t)BL * Cdim];
__device__ __align__(16) __half g_qkh [(size_t)BL * 2 * Cdim];
__device__ __align__(16) __half g_gh  [(size_t)BL * Cdim];
__device__ __align__(16) __half g_atth[(size_t)BL * Cdim];
__device__ __align__(16) float  g_kv  [BATCH * NHEAD * HDIM * HDIM];
__device__ __align__(16) float  g_km  [BATCH * NHEAD * HDIM];
__device__ __align__(16) __half g_wcat[Cdim * 2 * Cdim];   // [K,N] in_w|act_w
__device__ __align__(16) __half g_qkw [Cdim * 2 * Cdim];
__device__ __align__(16) __half g_outw[Cdim * Cdim];

// ---------------------------------------------------------------------------
__device__ __forceinline__ uint32_t smem_u32(const void* p) {
    return (uint32_t)__cvta_generic_to_shared(p);
}
__device__ __forceinline__ void ldm_x4(uint32_t& r0, uint32_t& r1, uint32_t& r2,
                                       uint32_t& r3, uint32_t a) {
    asm volatile("ldmatrix.sync.aligned.m8n8.x4.shared.b16 {%0,%1,%2,%3}, [%4];"
                 : "=r"(r0), "=r"(r1), "=r"(r2), "=r"(r3) : "r"(a));
}
__device__ __forceinline__ void ldm_x4t(uint32_t& r0, uint32_t& r1, uint32_t& r2,
                                        uint32_t& r3, uint32_t a) {
    asm volatile("ldmatrix.sync.aligned.m8n8.x4.trans.shared.b16 {%0,%1,%2,%3}, [%4];"
                 : "=r"(r0), "=r"(r1), "=r"(r2), "=r"(r3) : "r"(a));
}
__device__ __forceinline__ void mma_f16acc(uint32_t* c, uint32_t a0, uint32_t a1,
                                           uint32_t a2, uint32_t a3,
                                           uint32_t b0, uint32_t b1) {
    asm volatile(
        "mma.sync.aligned.m16n8k16.row.col.f16.f16.f16.f16 "
        "{%0,%1}, {%2,%3,%4,%5}, {%6,%7}, {%0,%1};"
        : "+r"(c[0]), "+r"(c[1])
        : "r"(a0), "r"(a1), "r"(a2), "r"(a3), "r"(b0), "r"(b1));
}
__device__ __forceinline__ void cpa16(uint32_t dst, const void* src) {
    asm volatile("cp.async.cg.shared.global [%0], [%1], 16;" :: "r"(dst), "l"(src));
}
__device__ __forceinline__ void cpa_commit() {
    asm volatile("cp.async.commit_group;" ::: "memory");
}
__device__ __forceinline__ void cpa_wait1() {
    asm volatile("cp.async.wait_group 1;" ::: "memory");
}
__device__ __forceinline__ void cpa_wait0() {
    asm volatile("cp.async.wait_group 0;" ::: "memory");
}
__device__ __forceinline__ __half2 packh2(float a, float b) {
    return __floats2half2_rn(a, b);
}
__device__ __forceinline__ float fast_silu(float v) {
    return __fdividef(v, 1.f + __expf(-v));
}
__device__ __forceinline__ float fast_elu1(float v) {
    return (v > 0.f) ? v + 1.f : __expf(v);
}

// ---------------------------------------------------------------------------
__global__ void convw_kernel(const float* __restrict__ in_w, const float* __restrict__ act_w,
                             const float* __restrict__ qk_w, const float* __restrict__ out_w)
{
    int i = blockIdx.x * 256 + threadIdx.x;
    if (i < Cdim * 2 * Cdim) {
        int r = i / (2 * Cdim), c = i % (2 * Cdim);
        float v = (c < Cdim) ? in_w[r * Cdim + c] : act_w[r * Cdim + (c - Cdim)];
        g_wcat[i] = __float2half(v);
        g_qkw[i]  = __float2half(qk_w[i]);
    }
    if (i < Cdim * Cdim) g_outw[i] = __float2half(out_w[i]);
    if (i < BATCH * NHEAD * HDIM * HDIM) g_kv[i] = 0.f;
    if (i < BATCH * NHEAD * HDIM) g_km[i] = 0.f;
}

// ---------------------------------------------------------------------------
__global__ void ln_kernel(const float* __restrict__ x, const float* __restrict__ gamma,
                          const float* __restrict__ beta, __half* __restrict__ out) {
    int row  = blockIdx.x * 8 + (threadIdx.x >> 5);
    int lane = threadIdx.x & 31;
    const float* xr = x + (size_t)row * Cdim;
    float v[6]; float s = 0.f, ss = 0.f;
#pragma unroll
    for (int i = 0; i < 6; i++) { v[i] = xr[lane + 32 * i]; s += v[i]; ss += v[i] * v[i]; }
#pragma unroll
    for (int o = 16; o > 0; o >>= 1) {
        s  += __shfl_xor_sync(0xffffffffu, s,  o);
        ss += __shfl_xor_sync(0xffffffffu, ss, o);
    }
    float mu   = s * (1.f / Cdim);
    float var  = ss * (1.f / Cdim) - mu * mu;
    float rstd = rsqrtf(var + LN_EPS);
    __half* orow = out + (size_t)row * Cdim;
#pragma unroll
    for (int i = 0; i < 6; i++) {
        int c = lane + 32 * i;
        orow[c] = __float2half((v[i] - mu) * rstd * gamma[c] + beta[c]);
    }
}

// ---------------------------------------------------------------------------
// Persistent weight-resident fp16 GEMM (f16 accumulate) — R13 verbatim.
// ---------------------------------------------------------------------------
constexpr int ASTR = 40, BSTR = 200;
constexpr int ASTAGE_B = 128 * ASTR * 2;
constexpr int BRES_B   = GK * BSTR * 2;
constexpr int SMEMP    = BRES_B + 2 * ASTAGE_B;   // 97280

template <int MODE>
__global__ __launch_bounds__(256, 1) void gemm_h(
    const __half* __restrict__ A, const __half* __restrict__ W,
    const float* __restrict__ bias1, const float* __restrict__ bias2,
    const float* __restrict__ resid,
    __half* __restrict__ Y1, __half* __restrict__ Y2,
    float* __restrict__ Yf, int N, int mtiles)
{
    extern __shared__ __align__(16) char smem[];
    uint32_t bs_base = smem_u32(smem);
    uint32_t as_base = bs_base + BRES_B;

    int tid  = threadIdx.x;
    int bn   = blockIdx.x * 192;
    int warp = tid >> 5, lane = tid & 31;
    int wm   = (warp & 3) * 32, wn = (warp >> 2) * 96;

#pragma unroll
    for (int i = 0; i < 18; i++) {
        int idx = i * 256 + tid;
        int r = idx / 24, c = idx % 24;
        cpa16(bs_base + (r * BSTR + c * 8) * 2, W + (size_t)r * N + bn + c * 8);
    }
    cpa_commit();

    auto load_a = [&](int stage, int bm, int kt) {
        uint32_t ab = as_base + stage * ASTAGE_B;
#pragma unroll
        for (int i = 0; i < 2; i++) {
            int idx = i * 256 + tid;
            int r = idx >> 2, c = idx & 3;
            cpa16(ab + (r * ASTR + c * 8) * 2,
                  A + (size_t)(bm + r) * GK + kt * 32 + c * 8);
        }
        cpa_commit();
    };

    int a_row = wm + (lane & 7) + ((lane >> 3) & 1) * 8;
    int a_col = (lane >> 4) * 8;
    int b_k   = (lane & 7) + ((lane >> 3) & 1) * 8;
    int b_n   = wn + (lane >> 4) * 8;
    int r0 = lane >> 2, c0 = (lane & 3) * 2;
    bool first = (blockIdx.x == 0);

    float bv[12][2];
    {
        const float* bsrc = (MODE == 0) ? (first ? bias1 : bias2) : bias1;
#pragma unroll
        for (int nt = 0; nt < 12; nt++) {
            int cl = wn + nt * 8 + c0;
            int bi = (MODE == 0) ? cl : bn + cl;
            bv[nt][0] = bsrc[bi];
            bv[nt][1] = bsrc[bi + 1];
        }
    }

    int mt = blockIdx.y;
    if (mt < mtiles) load_a(0, mt * 128, 0);

    for (; mt < mtiles; mt += gridDim.y) {
        int bm = mt * 128;
        int next_mt = mt + gridDim.y;

        uint32_t acc[2][12][2];
#pragma unroll
        for (int i = 0; i < 2; i++)
#pragma unroll
            for (int j = 0; j < 12; j++) { acc[i][j][0] = 0u; acc[i][j][1] = 0u; }

#pragma unroll
        for (int kt = 0; kt < 6; kt++) {
            bool has_next = (kt < 5) || (next_mt < mtiles);
            if (has_next) {
                if (kt < 5) load_a((kt + 1) & 1, bm, kt + 1);
                else        load_a(0, next_mt * 128, 0);
                cpa_wait1();
            } else {
                cpa_wait0();
            }
            __syncthreads();
            uint32_t ab = as_base + (kt & 1) * ASTAGE_B;
#pragma unroll
            for (int ks = 0; ks < 2; ks++) {
                uint32_t afr[2][4];
#pragma unroll
                for (int mti = 0; mti < 2; mti++) {
                    uint32_t addr = ab + ((a_row + mti * 16) * ASTR + a_col + ks * 16) * 2;
                    ldm_x4(afr[mti][0], afr[mti][1], afr[mti][2], afr[mti][3], addr);
                }
                uint32_t bfr[12][2];
#pragma unroll
                for (int p = 0; p < 6; p++) {
                    uint32_t addr = bs_base +
                        ((kt * 32 + ks * 16 + b_k) * BSTR + b_n + p * 16) * 2;
                    uint32_t t0, t1, t2, t3;
                    ldm_x4t(t0, t1, t2, t3, addr);
                    bfr[p * 2 + 0][0] = t0; bfr[p * 2 + 0][1] = t1;
                    bfr[p * 2 + 1][0] = t2; bfr[p * 2 + 1][1] = t3;
                }
#pragma unroll
                for (int mti = 0; mti < 2; mti++)
#pragma unroll
                    for (int nt = 0; nt < 12; nt++)
                        mma_f16acc(acc[mti][nt], afr[mti][0], afr[mti][1],
                                   afr[mti][2], afr[mti][3], bfr[nt][0], bfr[nt][1]);
            }
            __syncthreads();
        }

#pragma unroll
        for (int mti = 0; mti < 2; mti++) {
#pragma unroll
            for (int half = 0; half < 2; half++) {
                int row = bm + wm + mti * 16 + r0 + half * 8;
#pragma unroll
                for (int nt = 0; nt < 12; nt++) {
                    int cl = wn + nt * 8 + c0;
                    __half2 hv = *reinterpret_cast<__half2*>(&acc[mti][nt][half]);
                    float2 f = __half22float2(hv);
                    float v0 = f.x + bv[nt][0];
                    float v1 = f.y + bv[nt][1];
                    if (MODE == 0) {
                        if (!first) { v0 = fast_silu(v0); v1 = fast_silu(v1); }
                        __half* dst = first ? Y1 : Y2;
                        *(__half2*)&dst[(size_t)row * Cdim + cl] = packh2(v0, v1);
                    } else if (MODE == 1) {
                        v0 = fast_elu1(v0); v1 = fast_elu1(v1);
                        *(__half2*)&Y1[(size_t)row * N + bn + cl] = packh2(v0, v1);
                    } else {
                        float2 rr = *(const float2*)&resid[(size_t)row * N + bn + cl];
                        float2 o; o.x = v0 + rr.x; o.y = v1 + rr.y;
                        *(float2*)&Yf[(size_t)row * N + bn + cl] = o;
                    }
                }
            }
        }
    }
}

// ---------------------------------------------------------------------------
// Depthwise 3x3 + silu, 4x2 pixel tile per block (96 threads, 2ch each).
// grid = BATCH * (Himg/4) * (Wimg/2)
// ---------------------------------------------------------------------------
__global__ void dwconv_silu_kernel(const __half2* __restrict__ in,
                                   const float* __restrict__ w,
                                   const float* __restrict__ bias,
                                   __half2* __restrict__ out)
{
    int blk = blockIdx.x;
    int c2  = threadIdx.x;
    int xp  = blk % (Wimg / 2);
    int t   = blk / (Wimg / 2);
    int y4  = t % (Himg / 4);
    int b   = t / (Himg / 4);
    int x0  = xp * 2, y0 = y4 * 4;

    float2 wv[9];
#pragma unroll
    for (int i = 0; i < 9; i++) wv[i] = *(const float2*)&w[i * Cdim + 2 * c2];
    float2 bb = *(const float2*)&bias[2 * c2];
    float2 acc[4][2];
#pragma unroll
    for (int i = 0; i < 4; i++)
#pragma unroll
        for (int j = 0; j < 2; j++) acc[i][j] = bb;

#pragma unroll
    for (int rx = -1; rx < 3; rx++) {
        int xx = x0 + rx;
        if (xx < 0 || xx >= Wimg) continue;
#pragma unroll
        for (int ry = -1; ry < 5; ry++) {
            int yy = y0 + ry;
            if (yy < 0 || yy >= Himg) continue;
            float2 v = __half22float2(in[((size_t)(b * Himg + yy) * Wimg + xx) * 96 + c2]);
#pragma unroll
            for (int oy = 0; oy < 4; oy++) {
                int dy = ry - oy + 1;
                if (dy < 0 || dy >= 3) continue;
#pragma unroll
                for (int ox = 0; ox < 2; ox++) {
                    int dx = rx - ox + 1;
                    if (dx >= 0 && dx < 3) {
                        acc[oy][ox].x = fmaf(v.x, wv[dy * 3 + dx].x, acc[oy][ox].x);
                        acc[oy][ox].y = fmaf(v.y, wv[dy * 3 + dx].y, acc[oy][ox].y);
                    }
                }
            }
        }
    }
#pragma unroll
    for (int oy = 0; oy < 4; oy++)
#pragma unroll
        for (int ox = 0; ox < 2; ox++)
            out[((size_t)(b * Himg + y0 + oy) * Wimg + x0 + ox) * 96 + c2] =
                packh2(fast_silu(acc[oy][ox].x), fast_silu(acc[oy][ox].y));
}

// Fused: g = (att + dwconv(h)+lepe_b) * act_res, 4x2 tile
__global__ void lepe_mul_kernel(const __half2* __restrict__ hin,
                                const float* __restrict__ w,
                                const float* __restrict__ bias,
                                const __half2* __restrict__ att,
                                const __half2* __restrict__ actres,
                                __half2* __restrict__ out)
{
    int blk = blockIdx.x;
    int c2  = threadIdx.x;
    int xp  = blk % (Wimg / 2);
    int t   = blk / (Wimg / 2);
    int y4  = t % (Himg / 4);
    int b   = t / (Himg / 4);
    int x0  = xp * 2, y0 = y4 * 4;

    float2 wv[9];
#pragma unroll
    for (int i = 0; i < 9; i++) wv[i] = *(const float2*)&w[i * Cdim + 2 * c2];
    float2 bb = *(const float2*)&bias[2 * c2];
    float2 acc[4][2];
#pragma unroll
    for (int i = 0; i < 4; i++)
#pragma unroll
        for (int j = 0; j < 2; j++) acc[i][j] = bb;

#pragma unroll
    for (int rx = -1; rx < 3; rx++) {
        int xx = x0 + rx;
        if (xx < 0 || xx >= Wimg) continue;
#pragma unroll
        for (int ry = -1; ry < 5; ry++) {
            int yy = y0 + ry;
            if (yy < 0 || yy >= Himg) continue;
            float2 v = __half22float2(hin[((size_t)(b * Himg + yy) * Wimg + xx) * 96 + c2]);
#pragma unroll
            for (int oy = 0; oy < 4; oy++) {
                int dy = ry - oy + 1;
                if (dy < 0 || dy >= 3) continue;
#pragma unroll
                for (int ox = 0; ox < 2; ox++) {
                    int dx = rx - ox + 1;
                    if (dx >= 0 && dx < 3) {
                        acc[oy][ox].x = fmaf(v.x, wv[dy * 3 + dx].x, acc[oy][ox].x);
                        acc[oy][ox].y = fmaf(v.y, wv[dy * 3 + dx].y, acc[oy][ox].y);
                    }
                }
            }
        }
    }
#pragma unroll
    for (int oy = 0; oy < 4; oy++)
#pragma unroll
        for (int ox = 0; ox < 2; ox++) {
            size_t pix = (size_t)(b * Himg + y0 + oy) * Wimg + x0 + ox;
            float2 at = __half22float2(att[pix * 96 + c2]);
            float2 ar = __half22float2(actres[pix * 96 + c2]);
            out[pix * 96 + c2] = packh2((at.x + acc[oy][ox].x) * ar.x,
                                        (at.y + acc[oy][ox].y) * ar.y);
        }
}

// ---------------------------------------------------------------------------
// kv: 8-way split over L, partial sums atomically accumulated.
// ---------------------------------------------------------------------------
__global__ void kv_kernel(const __half* __restrict__ qk,
                          const __half* __restrict__ hv,
                          float* __restrict__ kv, float* __restrict__ km)
{
    int bh = blockIdx.x;
    int b = bh / NHEAD, hd = bh % NHEAD;
    __shared__ float skv[HDIM * HDIM];
    __shared__ float skm[HDIM];
    int tid = threadIdx.x;
    for (int i = tid; i < HDIM * HDIM; i += blockDim.x) skv[i] = 0.f;
    if (tid < HDIM) skm[tid] = 0.f;
    __syncthreads();

    int lane = tid & 31, warp = tid >> 5;
    const int per = Lseq / KVSPLIT;
    int n0 = blockIdx.y * per;

    float acc[HDIM];
#pragma unroll
    for (int e = 0; e < HDIM; e++) acc[e] = 0.f;
    float acck = 0.f;

    for (int n = n0 + warp; n < n0 + per; n += 8) {
        size_t rowq = (size_t)(b * Lseq + n) * (2 * Cdim);
        float kd = __half2float(qk[rowq + Cdim + hd * HDIM + lane]);
        float ve = __half2float(hv[(size_t)(b * Lseq + n) * Cdim + hd * HDIM + lane]);
        acck += kd;
#pragma unroll
        for (int e = 0; e < HDIM; e++)
            acc[e] = fmaf(kd, __shfl_sync(0xffffffffu, ve, e), acc[e]);
    }
#pragma unroll
    for (int e = 0; e < HDIM; e++) atomicAdd(&skv[lane * HDIM + e], acc[e]);
    atomicAdd(&skm[lane], acck);
    __syncthreads();

    const float invL = 1.f / (float)Lseq;
    for (int i = tid; i < HDIM * HDIM; i += blockDim.x)
        atomicAdd(&kv[(size_t)bh * HDIM * HDIM + i], skv[i] * invL);
    if (tid < HDIM) atomicAdd(&km[bh * HDIM + tid], skm[tid] * invL);
}

// ---------------------------------------------------------------------------
__global__ void att_kernel(const __half* __restrict__ qk,
                           const float* __restrict__ kv,
                           const float* __restrict__ km, __half* __restrict__ att)
{
    int bh = blockIdx.x;
    int b = bh / NHEAD, hd = bh % NHEAD;
    __shared__ float skv[HDIM * HDIM];
    __shared__ float skm[HDIM];
    int tid = threadIdx.x;
    for (int i = tid; i < HDIM * HDIM; i += blockDim.x)
        skv[i] = kv[(size_t)bh * HDIM * HDIM + i];
    if (tid < HDIM) skm[tid] = km[bh * HDIM + tid];
    __syncthreads();

    int lane = tid & 31, warp = tid >> 5;
    const int per = Lseq / 28;
    int n0 = blockIdx.y * per;
    for (int n = n0 + warp; n < n0 + per; n += 8) {
        float qe = __half2float(qk[(size_t)(b * Lseq + n) * (2 * Cdim) + hd * HDIM + lane]);
        float p = qe * skm[lane];
#pragma unroll
        for (int o = 16; o > 0; o >>= 1) p += __shfl_xor_sync(0xffffffffu, p, o);
        float z = __fdividef(1.f, p + 1e-6f);
        float a = 0.f;
#pragma unroll
        for (int d = 0; d < HDIM; d++)
            a = fmaf(__shfl_sync(0xffffffffu, qe, d), skv[d * HDIM + lane], a);
        att[(size_t)(b * Lseq + n) * Cdim + hd * HDIM + lane] = __float2half(a * z);
    }
}

// ---------------------------------------------------------------------------
extern "C" void kernel_launch(void* const* d_in, const int* in_sizes, int n_in,
                              void* d_out, int out_size)
{
    const float* x      = (const float*)d_in[0];
    const float* norm_g = (const float*)d_in[1];
    const float* norm_b = (const float*)d_in[2];
    const float* in_w   = (const float*)d_in[3];
    const float* in_b   = (const float*)d_in[4];
    const float* act_w  = (const float*)d_in[5];
    const float* act_b  = (const float*)d_in[6];
    const float* dwc_w  = (const float*)d_in[7];
    const float* dwc_b  = (const float*)d_in[8];
    const float* qk_w   = (const float*)d_in[9];
    const float* qk_b   = (const float*)d_in[10];
    const float* lepe_w = (const float*)d_in[11];
    const float* lepe_b = (const float*)d_in[12];
    const float* out_w  = (const float*)d_in[13];
    const float* out_b  = (const float*)d_in[14];
    float* out = (float*)d_out;

    __half *xnh, *h0h, *acth, *hh, *qkh, *gh, *atth, *wcat, *qkw, *outw;
    float *kv, *km;
    cudaGetSymbolAddress((void**)&xnh,  g_xnh);
    cudaGetSymbolAddress((void**)&h0h,  g_h0h);
    cudaGetSymbolAddress((void**)&acth, g_acth);
    cudaGetSymbolAddress((void**)&hh,   g_hh);
    cudaGetSymbolAddress((void**)&qkh,  g_qkh);
    cudaGetSymbolAddress((void**)&gh,   g_gh);
    cudaGetSymbolAddress((void**)&atth, g_atth);
    cudaGetSymbolAddress((void**)&kv,   g_kv);
    cudaGetSymbolAddress((void**)&km,   g_km);
    cudaGetSymbolAddress((void**)&wcat, g_wcat);
    cudaGetSymbolAddress((void**)&qkw,  g_qkw);
    cudaGetSymbolAddress((void**)&outw, g_outw);

    cudaFuncSetAttribute(gemm_h<0>, cudaFuncAttributeMaxDynamicSharedMemorySize, SMEMP);
    cudaFuncSetAttribute(gemm_h<1>, cudaFuncAttributeMaxDynamicSharedMemorySize, SMEMP);
    cudaFuncSetAttribute(gemm_h<2>, cudaFuncAttributeMaxDynamicSharedMemorySize, SMEMP);

    // 0) weights -> fp16 + zero kv/km accumulators
    convw_kernel<<<(Cdim * 2 * Cdim + 255) / 256, 256>>>(in_w, act_w, qk_w, out_w);

    // 1) LayerNorm -> fp16
    ln_kernel<<<BL / 8, 256>>>(x, norm_g, norm_b, xnh);

    const int MT = BL / 128;   // 392

    // 2) fused in-proj + act-proj (N=384, 2 resident weight slices)
    gemm_h<0><<<dim3(2, 74), 256, SMEMP>>>(
        xnh, wcat, in_b, act_b, nullptr, h0h, acth, nullptr, 2 * Cdim, MT);

    // 3) dwconv + silu -> h (4x2 pixel tiles)
    int dwgrid = BATCH * (Himg / 4) * (Wimg / 2);
    dwconv_silu_kernel<<<dwgrid, 96>>>((const __half2*)h0h, dwc_w, dwc_b,
                                       (__half2*)hh);

    // 4) qk-proj with elu+1 (N=384)
    gemm_h<1><<<dim3(2, 74), 256, SMEMP>>>(
        hh, qkw, qk_b, nullptr, nullptr, qkh, nullptr, nullptr, 2 * Cdim, MT);

    // 5) linear attention (split-8 kv, wide att grid)
    kv_kernel<<<dim3(BATCH * NHEAD, KVSPLIT), 256>>>(qkh, hh, kv, km);
    att_kernel<<<dim3(BATCH * NHEAD, 28), 256>>>(qkh, kv, km, atth);

    // 6) g = (att + lepe) * act_res -> gh (4x2 pixel tiles)
    lepe_mul_kernel<<<dwgrid, 96>>>((const __half2*)hh, lepe_w, lepe_b,
                                    (const __half2*)atth,
                                    (const __half2*)acth, (__half2*)gh);

    // 7) out-proj + bias + shortcut -> fp32 out
    gemm_h<2><<<dim3(1, 148), 256, SMEMP>>>(
        gh, outw, out_b, nullptr, x, nullptr, nullptr, out, Cdim, MT);
}

// round 15
// speedup vs baseline: 1.0754x; 1.0754x over previous
#include <cuda_runtime.h>
#include <cuda_fp16.h>
#include <stdint.h>
#include <math.h>

// ---------------------------------------------------------------------------
// EMLLA block, fp16. R13 structure (327.5us) with one change: GEMMs allow
// 2 CTAs/SM (drop launch_bounds minBlocks=1, double grid.y) to cover
// cp.async/barrier latency bubbles and the 392/74 tile-count tail imbalance.
// ---------------------------------------------------------------------------

constexpr int Himg = 56, Wimg = 56, Lseq = 3136, Cdim = 192;
constexpr int NHEAD = 6, HDIM = 32, BATCH = 16;
constexpr int BL = BATCH * Lseq;
constexpr float LN_EPS = 1e-5f;
constexpr int GK = 192;
constexpr int KVSPLIT = 4;

// Scratch (device globals: allocation-free, graph-capture safe)
__device__ __align__(16) __half g_xnh [(size_t)BL * Cdim];
__device__ __align__(16) __half g_h0h [(size_t)BL * Cdim];
__device__ __align__(16) __half g_acth[(size_t)BL * Cdim];
__device__ __align__(16) __half g_hh  [(size_t)BL * Cdim];
__device__ __align__(16) __half g_qkh [(size_t)BL * 2 * Cdim];
__device__ __align__(16) __half g_gh  [(size_t)BL * Cdim];
__device__ __align__(16) __half g_atth[(size_t)BL * Cdim];
__device__ __align__(16) float  g_kv  [BATCH * NHEAD * HDIM * HDIM];
__device__ __align__(16) float  g_km  [BATCH * NHEAD * HDIM];
__device__ __align__(16) __half g_wcat[Cdim * 2 * Cdim];   // [K,N] in_w|act_w
__device__ __align__(16) __half g_qkw [Cdim * 2 * Cdim];
__device__ __align__(16) __half g_outw[Cdim * Cdim];

// ---------------------------------------------------------------------------
__device__ __forceinline__ uint32_t smem_u32(const void* p) {
    return (uint32_t)__cvta_generic_to_shared(p);
}
__device__ __forceinline__ void ldm_x4(uint32_t& r0, uint32_t& r1, uint32_t& r2,
                                       uint32_t& r3, uint32_t a) {
    asm volatile("ldmatrix.sync.aligned.m8n8.x4.shared.b16 {%0,%1,%2,%3}, [%4];"
                 : "=r"(r0), "=r"(r1), "=r"(r2), "=r"(r3) : "r"(a));
}
__device__ __forceinline__ void ldm_x4t(uint32_t& r0, uint32_t& r1, uint32_t& r2,
                                        uint32_t& r3, uint32_t a) {
    asm volatile("ldmatrix.sync.aligned.m8n8.x4.trans.shared.b16 {%0,%1,%2,%3}, [%4];"
                 : "=r"(r0), "=r"(r1), "=r"(r2), "=r"(r3) : "r"(a));
}
__device__ __forceinline__ void mma_f16acc(uint32_t* c, uint32_t a0, uint32_t a1,
                                           uint32_t a2, uint32_t a3,
                                           uint32_t b0, uint32_t b1) {
    asm volatile(
        "mma.sync.aligned.m16n8k16.row.col.f16.f16.f16.f16 "
        "{%0,%1}, {%2,%3,%4,%5}, {%6,%7}, {%0,%1};"
        : "+r"(c[0]), "+r"(c[1])
        : "r"(a0), "r"(a1), "r"(a2), "r"(a3), "r"(b0), "r"(b1));
}
__device__ __forceinline__ void cpa16(uint32_t dst, const void* src) {
    asm volatile("cp.async.cg.shared.global [%0], [%1], 16;" :: "r"(dst), "l"(src));
}
__device__ __forceinline__ void cpa_commit() {
    asm volatile("cp.async.commit_group;" ::: "memory");
}
__device__ __forceinline__ void cpa_wait1() {
    asm volatile("cp.async.wait_group 1;" ::: "memory");
}
__device__ __forceinline__ void cpa_wait0() {
    asm volatile("cp.async.wait_group 0;" ::: "memory");
}
__device__ __forceinline__ __half2 packh2(float a, float b) {
    return __floats2half2_rn(a, b);
}
__device__ __forceinline__ float fast_silu(float v) {
    return __fdividef(v, 1.f + __expf(-v));
}
__device__ __forceinline__ float fast_elu1(float v) {
    return (v > 0.f) ? v + 1.f : __expf(v);
}

// ---------------------------------------------------------------------------
__global__ void convw_kernel(const float* __restrict__ in_w, const float* __restrict__ act_w,
                             const float* __restrict__ qk_w, const float* __restrict__ out_w)
{
    int i = blockIdx.x * 256 + threadIdx.x;
    if (i < Cdim * 2 * Cdim) {
        int r = i / (2 * Cdim), c = i % (2 * Cdim);
        float v = (c < Cdim) ? in_w[r * Cdim + c] : act_w[r * Cdim + (c - Cdim)];
        g_wcat[i] = __float2half(v);
        g_qkw[i]  = __float2half(qk_w[i]);
    }
    if (i < Cdim * Cdim) g_outw[i] = __float2half(out_w[i]);
    if (i < BATCH * NHEAD * HDIM * HDIM) g_kv[i] = 0.f;
    if (i < BATCH * NHEAD * HDIM) g_km[i] = 0.f;
}

// ---------------------------------------------------------------------------
__global__ void ln_kernel(const float* __restrict__ x, const float* __restrict__ gamma,
                          const float* __restrict__ beta, __half* __restrict__ out) {
    int row  = blockIdx.x * 8 + (threadIdx.x >> 5);
    int lane = threadIdx.x & 31;
    const float* xr = x + (size_t)row * Cdim;
    float v[6]; float s = 0.f, ss = 0.f;
#pragma unroll
    for (int i = 0; i < 6; i++) { v[i] = xr[lane + 32 * i]; s += v[i]; ss += v[i] * v[i]; }
#pragma unroll
    for (int o = 16; o > 0; o >>= 1) {
        s  += __shfl_xor_sync(0xffffffffu, s,  o);
        ss += __shfl_xor_sync(0xffffffffu, ss, o);
    }
    float mu   = s * (1.f / Cdim);
    float var  = ss * (1.f / Cdim) - mu * mu;
    float rstd = rsqrtf(var + LN_EPS);
    __half* orow = out + (size_t)row * Cdim;
#pragma unroll
    for (int i = 0; i < 6; i++) {
        int c = lane + 32 * i;
        orow[c] = __float2half((v[i] - mu) * rstd * gamma[c] + beta[c]);
    }
}

// ---------------------------------------------------------------------------
// Persistent weight-resident fp16 GEMM (f16 accumulate). 2 CTAs/SM allowed.
// ---------------------------------------------------------------------------
constexpr int ASTR = 40, BSTR = 200;
constexpr int ASTAGE_B = 128 * ASTR * 2;
constexpr int BRES_B   = GK * BSTR * 2;
constexpr int SMEMP    = BRES_B + 2 * ASTAGE_B;   // 97280 (x2 = 194.5KB < 228KB)

template <int MODE>
__global__ __launch_bounds__(256) void gemm_h(
    const __half* __restrict__ A, const __half* __restrict__ W,
    const float* __restrict__ bias1, const float* __restrict__ bias2,
    const float* __restrict__ resid,
    __half* __restrict__ Y1, __half* __restrict__ Y2,
    float* __restrict__ Yf, int N, int mtiles)
{
    extern __shared__ __align__(16) char smem[];
    uint32_t bs_base = smem_u32(smem);
    uint32_t as_base = bs_base + BRES_B;

    int tid  = threadIdx.x;
    int bn   = blockIdx.x * 192;
    int warp = tid >> 5, lane = tid & 31;
    int wm   = (warp & 3) * 32, wn = (warp >> 2) * 96;

#pragma unroll
    for (int i = 0; i < 18; i++) {
        int idx = i * 256 + tid;
        int r = idx / 24, c = idx % 24;
        cpa16(bs_base + (r * BSTR + c * 8) * 2, W + (size_t)r * N + bn + c * 8);
    }
    cpa_commit();

    auto load_a = [&](int stage, int bm, int kt) {
        uint32_t ab = as_base + stage * ASTAGE_B;
#pragma unroll
        for (int i = 0; i < 2; i++) {
            int idx = i * 256 + tid;
            int r = idx >> 2, c = idx & 3;
            cpa16(ab + (r * ASTR + c * 8) * 2,
                  A + (size_t)(bm + r) * GK + kt * 32 + c * 8);
        }
        cpa_commit();
    };

    int a_row = wm + (lane & 7) + ((lane >> 3) & 1) * 8;
    int a_col = (lane >> 4) * 8;
    int b_k   = (lane & 7) + ((lane >> 3) & 1) * 8;
    int b_n   = wn + (lane >> 4) * 8;
    int r0 = lane >> 2, c0 = (lane & 3) * 2;
    bool first = (blockIdx.x == 0);

    float bv[12][2];
    {
        const float* bsrc = (MODE == 0) ? (first ? bias1 : bias2) : bias1;
#pragma unroll
        for (int nt = 0; nt < 12; nt++) {
            int cl = wn + nt * 8 + c0;
            int bi = (MODE == 0) ? cl : bn + cl;
            bv[nt][0] = bsrc[bi];
            bv[nt][1] = bsrc[bi + 1];
        }
    }

    int mt = blockIdx.y;
    if (mt < mtiles) load_a(0, mt * 128, 0);

    for (; mt < mtiles; mt += gridDim.y) {
        int bm = mt * 128;
        int next_mt = mt + gridDim.y;

        uint32_t acc[2][12][2];
#pragma unroll
        for (int i = 0; i < 2; i++)
#pragma unroll
            for (int j = 0; j < 12; j++) { acc[i][j][0] = 0u; acc[i][j][1] = 0u; }

#pragma unroll
        for (int kt = 0; kt < 6; kt++) {
            bool has_next = (kt < 5) || (next_mt < mtiles);
            if (has_next) {
                if (kt < 5) load_a((kt + 1) & 1, bm, kt + 1);
                else        load_a(0, next_mt * 128, 0);
                cpa_wait1();
            } else {
                cpa_wait0();
            }
            __syncthreads();
            uint32_t ab = as_base + (kt & 1) * ASTAGE_B;
#pragma unroll
            for (int ks = 0; ks < 2; ks++) {
                uint32_t afr[2][4];
#pragma unroll
                for (int mti = 0; mti < 2; mti++) {
                    uint32_t addr = ab + ((a_row + mti * 16) * ASTR + a_col + ks * 16) * 2;
                    ldm_x4(afr[mti][0], afr[mti][1], afr[mti][2], afr[mti][3], addr);
                }
                uint32_t bfr[12][2];
#pragma unroll
                for (int p = 0; p < 6; p++) {
                    uint32_t addr = bs_base +
                        ((kt * 32 + ks * 16 + b_k) * BSTR + b_n + p * 16) * 2;
                    uint32_t t0, t1, t2, t3;
                    ldm_x4t(t0, t1, t2, t3, addr);
                    bfr[p * 2 + 0][0] = t0; bfr[p * 2 + 0][1] = t1;
                    bfr[p * 2 + 1][0] = t2; bfr[p * 2 + 1][1] = t3;
                }
#pragma unroll
                for (int mti = 0; mti < 2; mti++)
#pragma unroll
                    for (int nt = 0; nt < 12; nt++)
                        mma_f16acc(acc[mti][nt], afr[mti][0], afr[mti][1],
                                   afr[mti][2], afr[mti][3], bfr[nt][0], bfr[nt][1]);
            }
            __syncthreads();
        }

#pragma unroll
        for (int mti = 0; mti < 2; mti++) {
#pragma unroll
            for (int half = 0; half < 2; half++) {
                int row = bm + wm + mti * 16 + r0 + half * 8;
#pragma unroll
                for (int nt = 0; nt < 12; nt++) {
                    int cl = wn + nt * 8 + c0;
                    __half2 hv = *reinterpret_cast<__half2*>(&acc[mti][nt][half]);
                    float2 f = __half22float2(hv);
                    float v0 = f.x + bv[nt][0];
                    float v1 = f.y + bv[nt][1];
                    if (MODE == 0) {
                        if (!first) { v0 = fast_silu(v0); v1 = fast_silu(v1); }
                        __half* dst = first ? Y1 : Y2;
                        *(__half2*)&dst[(size_t)row * Cdim + cl] = packh2(v0, v1);
                    } else if (MODE == 1) {
                        v0 = fast_elu1(v0); v1 = fast_elu1(v1);
                        *(__half2*)&Y1[(size_t)row * N + bn + cl] = packh2(v0, v1);
                    } else {
                        float2 rr = *(const float2*)&resid[(size_t)row * N + bn + cl];
                        float2 o; o.x = v0 + rr.x; o.y = v1 + rr.y;
                        *(float2*)&Yf[(size_t)row * N + bn + cl] = o;
                    }
                }
            }
        }
    }
}

// ---------------------------------------------------------------------------
// Depthwise 3x3 + silu (R13 4x1 tiles)
// ---------------------------------------------------------------------------
__global__ void dwconv_silu_kernel(const __half2* __restrict__ in,
                                   const float* __restrict__ w,
                                   const float* __restrict__ bias,
                                   __half2* __restrict__ out)
{
    int blk = blockIdx.x;
    int c2  = threadIdx.x;
    int x   = blk % Wimg;
    int t   = blk / Wimg;
    int y4  = t % (Himg / 4);
    int b   = t / (Himg / 4);
    int y0  = y4 * 4;

    float2 wv[9];
#pragma unroll
    for (int i = 0; i < 9; i++) wv[i] = *(const float2*)&w[i * Cdim + 2 * c2];
    float2 bb = *(const float2*)&bias[2 * c2];
    float2 acc[4];
#pragma unroll
    for (int i = 0; i < 4; i++) acc[i] = bb;

#pragma unroll
    for (int dx = 0; dx < 3; dx++) {
        int xx = x + dx - 1;
        if (xx < 0 || xx >= Wimg) continue;
#pragma unroll
        for (int ry = -1; ry < 5; ry++) {
            int yy = y0 + ry;
            if (yy < 0 || yy >= Himg) continue;
            float2 v = __half22float2(in[((size_t)(b * Himg + yy) * Wimg + xx) * 96 + c2]);
#pragma unroll
            for (int oy = 0; oy < 4; oy++) {
                int dy = ry - oy + 1;
                if (dy >= 0 && dy < 3) {
                    acc[oy].x = fmaf(v.x, wv[dy * 3 + dx].x, acc[oy].x);
                    acc[oy].y = fmaf(v.y, wv[dy * 3 + dx].y, acc[oy].y);
                }
            }
        }
    }
#pragma unroll
    for (int oy = 0; oy < 4; oy++) {
        out[((size_t)(b * Himg + y0 + oy) * Wimg + x) * 96 + c2] =
            packh2(fast_silu(acc[oy].x), fast_silu(acc[oy].y));
    }
}

// Fused: g = (att + dwconv(h)+lepe_b) * act_res (R13 4x1)
__global__ void lepe_mul_kernel(const __half2* __restrict__ hin,
                                const float* __restrict__ w,
                                const float* __restrict__ bias,
                                const __half2* __restrict__ att,
                                const __half2* __restrict__ actres,
                                __half2* __restrict__ out)
{
    int blk = blockIdx.x;
    int c2  = threadIdx.x;
    int x   = blk % Wimg;
    int t   = blk / Wimg;
    int y4  = t % (Himg / 4);
    int b   = t / (Himg / 4);
    int y0  = y4 * 4;

    float2 wv[9];
#pragma unroll
    for (int i = 0; i < 9; i++) wv[i] = *(const float2*)&w[i * Cdim + 2 * c2];
    float2 bb = *(const float2*)&bias[2 * c2];
    float2 acc[4];
#pragma unroll
    for (int i = 0; i < 4; i++) acc[i] = bb;

#pragma unroll
    for (int dx = 0; dx < 3; dx++) {
        int xx = x + dx - 1;
        if (xx < 0 || xx >= Wimg) continue;
#pragma unroll
        for (int ry = -1; ry < 5; ry++) {
            int yy = y0 + ry;
            if (yy < 0 || yy >= Himg) continue;
            float2 v = __half22float2(hin[((size_t)(b * Himg + yy) * Wimg + xx) * 96 + c2]);
#pragma unroll
            for (int oy = 0; oy < 4; oy++) {
                int dy = ry - oy + 1;
                if (dy >= 0 && dy < 3) {
                    acc[oy].x = fmaf(v.x, wv[dy * 3 + dx].x, acc[oy].x);
                    acc[oy].y = fmaf(v.y, wv[dy * 3 + dx].y, acc[oy].y);
                }
            }
        }
    }
#pragma unroll
    for (int oy = 0; oy < 4; oy++) {
        size_t pix = (size_t)(b * Himg + y0 + oy) * Wimg + x;
        float2 at = __half22float2(att[pix * 96 + c2]);
        float2 ar = __half22float2(actres[pix * 96 + c2]);
        out[pix * 96 + c2] = packh2((at.x + acc[oy].x) * ar.x,
                                    (at.y + acc[oy].y) * ar.y);
    }
}

// ---------------------------------------------------------------------------
// kv: 4-way split over L (R13), partials atomically accumulated.
// ---------------------------------------------------------------------------
__global__ void kv_kernel(const __half* __restrict__ qk,
                          const __half* __restrict__ hv,
                          float* __restrict__ kv, float* __restrict__ km)
{
    int bh = blockIdx.x;
    int b = bh / NHEAD, hd = bh % NHEAD;
    __shared__ float skv[HDIM * HDIM];
    __shared__ float skm[HDIM];
    int tid = threadIdx.x;
    for (int i = tid; i < HDIM * HDIM; i += blockDim.x) skv[i] = 0.f;
    if (tid < HDIM) skm[tid] = 0.f;
    __syncthreads();

    int lane = tid & 31, warp = tid >> 5;
    const int per = Lseq / KVSPLIT;
    int n0 = blockIdx.y * per;

    float acc[HDIM];
#pragma unroll
    for (int e = 0; e < HDIM; e++) acc[e] = 0.f;
    float acck = 0.f;

    for (int n = n0 + warp; n < n0 + per; n += 8) {
        size_t rowq = (size_t)(b * Lseq + n) * (2 * Cdim);
        float kd = __half2float(qk[rowq + Cdim + hd * HDIM + lane]);
        float ve = __half2float(hv[(size_t)(b * Lseq + n) * Cdim + hd * HDIM + lane]);
        acck += kd;
#pragma unroll
        for (int e = 0; e < HDIM; e++)
            acc[e] = fmaf(kd, __shfl_sync(0xffffffffu, ve, e), acc[e]);
    }
#pragma unroll
    for (int e = 0; e < HDIM; e++) atomicAdd(&skv[lane * HDIM + e], acc[e]);
    atomicAdd(&skm[lane], acck);
    __syncthreads();

    const float invL = 1.f / (float)Lseq;
    for (int i = tid; i < HDIM * HDIM; i += blockDim.x)
        atomicAdd(&kv[(size_t)bh * HDIM * HDIM + i], skv[i] * invL);
    if (tid < HDIM) atomicAdd(&km[bh * HDIM + tid], skm[tid] * invL);
}

// ---------------------------------------------------------------------------
__global__ void att_kernel(const __half* __restrict__ qk,
                           const float* __restrict__ kv,
                           const float* __restrict__ km, __half* __restrict__ att)
{
    int bh = blockIdx.x;
    int b = bh / NHEAD, hd = bh % NHEAD;
    __shared__ float skv[HDIM * HDIM];
    __shared__ float skm[HDIM];
    int tid = threadIdx.x;
    for (int i = tid; i < HDIM * HDIM; i += blockDim.x)
        skv[i] = kv[(size_t)bh * HDIM * HDIM + i];
    if (tid < HDIM) skm[tid] = km[bh * HDIM + tid];
    __syncthreads();

    int lane = tid & 31, warp = tid >> 5;
    const int per = Lseq / 8;
    int n0 = blockIdx.y * per;
    for (int n = n0 + warp; n < n0 + per; n += 8) {
        float qe = __half2float(qk[(size_t)(b * Lseq + n) * (2 * Cdim) + hd * HDIM + lane]);
        float p = qe * skm[lane];
#pragma unroll
        for (int o = 16; o > 0; o >>= 1) p += __shfl_xor_sync(0xffffffffu, p, o);
        float z = __fdividef(1.f, p + 1e-6f);
        float a = 0.f;
#pragma unroll
        for (int d = 0; d < HDIM; d++)
            a = fmaf(__shfl_sync(0xffffffffu, qe, d), skv[d * HDIM + lane], a);
        att[(size_t)(b * Lseq + n) * Cdim + hd * HDIM + lane] = __float2half(a * z);
    }
}

// ---------------------------------------------------------------------------
extern "C" void kernel_launch(void* const* d_in, const int* in_sizes, int n_in,
                              void* d_out, int out_size)
{
    const float* x      = (const float*)d_in[0];
    const float* norm_g = (const float*)d_in[1];
    const float* norm_b = (const float*)d_in[2];
    const float* in_w   = (const float*)d_in[3];
    const float* in_b   = (const float*)d_in[4];
    const float* act_w  = (const float*)d_in[5];
    const float* act_b  = (const float*)d_in[6];
    const float* dwc_w  = (const float*)d_in[7];
    const float* dwc_b  = (const float*)d_in[8];
    const float* qk_w   = (const float*)d_in[9];
    const float* qk_b   = (const float*)d_in[10];
    const float* lepe_w = (const float*)d_in[11];
    const float* lepe_b = (const float*)d_in[12];
    const float* out_w  = (const float*)d_in[13];
    const float* out_b  = (const float*)d_in[14];
    float* out = (float*)d_out;

    __half *xnh, *h0h, *acth, *hh, *qkh, *gh, *atth, *wcat, *qkw, *outw;
    float *kv, *km;
    cudaGetSymbolAddress((void**)&xnh,  g_xnh);
    cudaGetSymbolAddress((void**)&h0h,  g_h0h);
    cudaGetSymbolAddress((void**)&acth, g_acth);
    cudaGetSymbolAddress((void**)&hh,   g_hh);
    cudaGetSymbolAddress((void**)&qkh,  g_qkh);
    cudaGetSymbolAddress((void**)&gh,   g_gh);
    cudaGetSymbolAddress((void**)&atth, g_atth);
    cudaGetSymbolAddress((void**)&kv,   g_kv);
    cudaGetSymbolAddress((void**)&km,   g_km);
    cudaGetSymbolAddress((void**)&wcat, g_wcat);
    cudaGetSymbolAddress((void**)&qkw,  g_qkw);
    cudaGetSymbolAddress((void**)&outw, g_outw);

    cudaFuncSetAttribute(gemm_h<0>, cudaFuncAttributeMaxDynamicSharedMemorySize, SMEMP);
    cudaFuncSetAttribute(gemm_h<1>, cudaFuncAttributeMaxDynamicSharedMemorySize, SMEMP);
    cudaFuncSetAttribute(gemm_h<2>, cudaFuncAttributeMaxDynamicSharedMemorySize, SMEMP);

    // 0) weights -> fp16 + zero kv/km accumulators
    convw_kernel<<<(Cdim * 2 * Cdim + 255) / 256, 256>>>(in_w, act_w, qk_w, out_w);

    // 1) LayerNorm -> fp16
    ln_kernel<<<BL / 8, 256>>>(x, norm_g, norm_b, xnh);

    const int MT = BL / 128;   // 392

    // 2) fused in-proj + act-proj (N=384) — 2 CTAs/SM
    gemm_h<0><<<dim3(2, 148), 256, SMEMP>>>(
        xnh, wcat, in_b, act_b, nullptr, h0h, acth, nullptr, 2 * Cdim, MT);

    // 3) dwconv + silu -> h
    int dwgrid = BATCH * (Himg / 4) * Wimg;
    dwconv_silu_kernel<<<dwgrid, 96>>>((const __half2*)h0h, dwc_w, dwc_b,
                                       (__half2*)hh);

    // 4) qk-proj with elu+1 (N=384) — 2 CTAs/SM
    gemm_h<1><<<dim3(2, 148), 256, SMEMP>>>(
        hh, qkw, qk_b, nullptr, nullptr, qkh, nullptr, nullptr, 2 * Cdim, MT);

    // 5) linear attention (split-4 kv + fp16 att)
    kv_kernel<<<dim3(BATCH * NHEAD, KVSPLIT), 256>>>(qkh, hh, kv, km);
    att_kernel<<<dim3(BATCH * NHEAD, 8), 256>>>(qkh, kv, km, atth);

    // 6) g = (att + lepe) * act_res -> gh
    lepe_mul_kernel<<<dwgrid, 96>>>((const __half2*)hh, lepe_w, lepe_b,
                                    (const __half2*)atth,
                                    (const __half2*)acth, (__half2*)gh);

    // 7) out-proj + bias + shortcut -> fp32 out — 2 CTAs/SM
    gemm_h<2><<<dim3(1, 296), 256, SMEMP>>>(
        gh, outw, out_b, nullptr, x, nullptr, nullptr, out, Cdim, MT);
}

// round 16
// speedup vs baseline: 1.0812x; 1.0054x over previous
#include <cuda_runtime.h>
#include <cuda_fp16.h>
#include <stdint.h>
#include <math.h>

// ---------------------------------------------------------------------------
// EMLLA block, fp16. R15 structure (322.0us): persistent mma.sync GEMMs at
// 2 CTAs/SM (established floor), split-4 kv, fp16 att. This round: dwconv and
// lepe inner loops use native __hfma2 half2 arithmetic (2 ch/instr, no
// half<->float converts) — they were issue-bound at 2x needed FMA work.
// ---------------------------------------------------------------------------

constexpr int Himg = 56, Wimg = 56, Lseq = 3136, Cdim = 192;
constexpr int NHEAD = 6, HDIM = 32, BATCH = 16;
constexpr int BL = BATCH * Lseq;
constexpr float LN_EPS = 1e-5f;
constexpr int GK = 192;
constexpr int KVSPLIT = 4;

// Scratch (device globals: allocation-free, graph-capture safe)
__device__ __align__(16) __half g_xnh [(size_t)BL * Cdim];
__device__ __align__(16) __half g_h0h [(size_t)BL * Cdim];
__device__ __align__(16) __half g_acth[(size_t)BL * Cdim];
__device__ __align__(16) __half g_hh  [(size_t)BL * Cdim];
__device__ __align__(16) __half g_qkh [(size_t)BL * 2 * Cdim];
__device__ __align__(16) __half g_gh  [(size_t)BL * Cdim];
__device__ __align__(16) __half g_atth[(size_t)BL * Cdim];
__device__ __align__(16) float  g_kv  [BATCH * NHEAD * HDIM * HDIM];
__device__ __align__(16) float  g_km  [BATCH * NHEAD * HDIM];
__device__ __align__(16) __half g_wcat[Cdim * 2 * Cdim];   // [K,N] in_w|act_w
__device__ __align__(16) __half g_qkw [Cdim * 2 * Cdim];
__device__ __align__(16) __half g_outw[Cdim * Cdim];

// ---------------------------------------------------------------------------
__device__ __forceinline__ uint32_t smem_u32(const void* p) {
    return (uint32_t)__cvta_generic_to_shared(p);
}
__device__ __forceinline__ void ldm_x4(uint32_t& r0, uint32_t& r1, uint32_t& r2,
                                       uint32_t& r3, uint32_t a) {
    asm volatile("ldmatrix.sync.aligned.m8n8.x4.shared.b16 {%0,%1,%2,%3}, [%4];"
                 : "=r"(r0), "=r"(r1), "=r"(r2), "=r"(r3) : "r"(a));
}
__device__ __forceinline__ void ldm_x4t(uint32_t& r0, uint32_t& r1, uint32_t& r2,
                                        uint32_t& r3, uint32_t a) {
    asm volatile("ldmatrix.sync.aligned.m8n8.x4.trans.shared.b16 {%0,%1,%2,%3}, [%4];"
                 : "=r"(r0), "=r"(r1), "=r"(r2), "=r"(r3) : "r"(a));
}
__device__ __forceinline__ void mma_f16acc(uint32_t* c, uint32_t a0, uint32_t a1,
                                           uint32_t a2, uint32_t a3,
                                           uint32_t b0, uint32_t b1) {
    asm volatile(
        "mma.sync.aligned.m16n8k16.row.col.f16.f16.f16.f16 "
        "{%0,%1}, {%2,%3,%4,%5}, {%6,%7}, {%0,%1};"
        : "+r"(c[0]), "+r"(c[1])
        : "r"(a0), "r"(a1), "r"(a2), "r"(a3), "r"(b0), "r"(b1));
}
__device__ __forceinline__ void cpa16(uint32_t dst, const void* src) {
    asm volatile("cp.async.cg.shared.global [%0], [%1], 16;" :: "r"(dst), "l"(src));
}
__device__ __forceinline__ void cpa_commit() {
    asm volatile("cp.async.commit_group;" ::: "memory");
}
__device__ __forceinline__ void cpa_wait1() {
    asm volatile("cp.async.wait_group 1;" ::: "memory");
}
__device__ __forceinline__ void cpa_wait0() {
    asm volatile("cp.async.wait_group 0;" ::: "memory");
}
__device__ __forceinline__ __half2 packh2(float a, float b) {
    return __floats2half2_rn(a, b);
}
__device__ __forceinline__ float fast_silu(float v) {
    return __fdividef(v, 1.f + __expf(-v));
}
__device__ __forceinline__ float fast_elu1(float v) {
    return (v > 0.f) ? v + 1.f : __expf(v);
}

// ---------------------------------------------------------------------------
__global__ void convw_kernel(const float* __restrict__ in_w, const float* __restrict__ act_w,
                             const float* __restrict__ qk_w, const float* __restrict__ out_w)
{
    int i = blockIdx.x * 256 + threadIdx.x;
    if (i < Cdim * 2 * Cdim) {
        int r = i / (2 * Cdim), c = i % (2 * Cdim);
        float v = (c < Cdim) ? in_w[r * Cdim + c] : act_w[r * Cdim + (c - Cdim)];
        g_wcat[i] = __float2half(v);
        g_qkw[i]  = __float2half(qk_w[i]);
    }
    if (i < Cdim * Cdim) g_outw[i] = __float2half(out_w[i]);
    if (i < BATCH * NHEAD * HDIM * HDIM) g_kv[i] = 0.f;
    if (i < BATCH * NHEAD * HDIM) g_km[i] = 0.f;
}

// ---------------------------------------------------------------------------
__global__ void ln_kernel(const float* __restrict__ x, const float* __restrict__ gamma,
                          const float* __restrict__ beta, __half* __restrict__ out) {
    int row  = blockIdx.x * 8 + (threadIdx.x >> 5);
    int lane = threadIdx.x & 31;
    const float* xr = x + (size_t)row * Cdim;
    float v[6]; float s = 0.f, ss = 0.f;
#pragma unroll
    for (int i = 0; i < 6; i++) { v[i] = xr[lane + 32 * i]; s += v[i]; ss += v[i] * v[i]; }
#pragma unroll
    for (int o = 16; o > 0; o >>= 1) {
        s  += __shfl_xor_sync(0xffffffffu, s,  o);
        ss += __shfl_xor_sync(0xffffffffu, ss, o);
    }
    float mu   = s * (1.f / Cdim);
    float var  = ss * (1.f / Cdim) - mu * mu;
    float rstd = rsqrtf(var + LN_EPS);
    __half* orow = out + (size_t)row * Cdim;
#pragma unroll
    for (int i = 0; i < 6; i++) {
        int c = lane + 32 * i;
        orow[c] = __float2half((v[i] - mu) * rstd * gamma[c] + beta[c]);
    }
}

// ---------------------------------------------------------------------------
// Persistent weight-resident fp16 GEMM (f16 accumulate). 2 CTAs/SM.
// ---------------------------------------------------------------------------
constexpr int ASTR = 40, BSTR = 200;
constexpr int ASTAGE_B = 128 * ASTR * 2;
constexpr int BRES_B   = GK * BSTR * 2;
constexpr int SMEMP    = BRES_B + 2 * ASTAGE_B;   // 97280 (x2 = 194.5KB < 228KB)

template <int MODE>
__global__ __launch_bounds__(256) void gemm_h(
    const __half* __restrict__ A, const __half* __restrict__ W,
    const float* __restrict__ bias1, const float* __restrict__ bias2,
    const float* __restrict__ resid,
    __half* __restrict__ Y1, __half* __restrict__ Y2,
    float* __restrict__ Yf, int N, int mtiles)
{
    extern __shared__ __align__(16) char smem[];
    uint32_t bs_base = smem_u32(smem);
    uint32_t as_base = bs_base + BRES_B;

    int tid  = threadIdx.x;
    int bn   = blockIdx.x * 192;
    int warp = tid >> 5, lane = tid & 31;
    int wm   = (warp & 3) * 32, wn = (warp >> 2) * 96;

#pragma unroll
    for (int i = 0; i < 18; i++) {
        int idx = i * 256 + tid;
        int r = idx / 24, c = idx % 24;
        cpa16(bs_base + (r * BSTR + c * 8) * 2, W + (size_t)r * N + bn + c * 8);
    }
    cpa_commit();

    auto load_a = [&](int stage, int bm, int kt) {
        uint32_t ab = as_base + stage * ASTAGE_B;
#pragma unroll
        for (int i = 0; i < 2; i++) {
            int idx = i * 256 + tid;
            int r = idx >> 2, c = idx & 3;
            cpa16(ab + (r * ASTR + c * 8) * 2,
                  A + (size_t)(bm + r) * GK + kt * 32 + c * 8);
        }
        cpa_commit();
    };

    int a_row = wm + (lane & 7) + ((lane >> 3) & 1) * 8;
    int a_col = (lane >> 4) * 8;
    int b_k   = (lane & 7) + ((lane >> 3) & 1) * 8;
    int b_n   = wn + (lane >> 4) * 8;
    int r0 = lane >> 2, c0 = (lane & 3) * 2;
    bool first = (blockIdx.x == 0);

    float bv[12][2];
    {
        const float* bsrc = (MODE == 0) ? (first ? bias1 : bias2) : bias1;
#pragma unroll
        for (int nt = 0; nt < 12; nt++) {
            int cl = wn + nt * 8 + c0;
            int bi = (MODE == 0) ? cl : bn + cl;
            bv[nt][0] = bsrc[bi];
            bv[nt][1] = bsrc[bi + 1];
        }
    }

    int mt = blockIdx.y;
    if (mt < mtiles) load_a(0, mt * 128, 0);

    for (; mt < mtiles; mt += gridDim.y) {
        int bm = mt * 128;
        int next_mt = mt + gridDim.y;

        uint32_t acc[2][12][2];
#pragma unroll
        for (int i = 0; i < 2; i++)
#pragma unroll
            for (int j = 0; j < 12; j++) { acc[i][j][0] = 0u; acc[i][j][1] = 0u; }

#pragma unroll
        for (int kt = 0; kt < 6; kt++) {
            bool has_next = (kt < 5) || (next_mt < mtiles);
            if (has_next) {
                if (kt < 5) load_a((kt + 1) & 1, bm, kt + 1);
                else        load_a(0, next_mt * 128, 0);
                cpa_wait1();
            } else {
                cpa_wait0();
            }
            __syncthreads();
            uint32_t ab = as_base + (kt & 1) * ASTAGE_B;
#pragma unroll
            for (int ks = 0; ks < 2; ks++) {
                uint32_t afr[2][4];
#pragma unroll
                for (int mti = 0; mti < 2; mti++) {
                    uint32_t addr = ab + ((a_row + mti * 16) * ASTR + a_col + ks * 16) * 2;
                    ldm_x4(afr[mti][0], afr[mti][1], afr[mti][2], afr[mti][3], addr);
                }
                uint32_t bfr[12][2];
#pragma unroll
                for (int p = 0; p < 6; p++) {
                    uint32_t addr = bs_base +
                        ((kt * 32 + ks * 16 + b_k) * BSTR + b_n + p * 16) * 2;
                    uint32_t t0, t1, t2, t3;
                    ldm_x4t(t0, t1, t2, t3, addr);
                    bfr[p * 2 + 0][0] = t0; bfr[p * 2 + 0][1] = t1;
                    bfr[p * 2 + 1][0] = t2; bfr[p * 2 + 1][1] = t3;
                }
#pragma unroll
                for (int mti = 0; mti < 2; mti++)
#pragma unroll
                    for (int nt = 0; nt < 12; nt++)
                        mma_f16acc(acc[mti][nt], afr[mti][0], afr[mti][1],
                                   afr[mti][2], afr[mti][3], bfr[nt][0], bfr[nt][1]);
            }
            __syncthreads();
        }

#pragma unroll
        for (int mti = 0; mti < 2; mti++) {
#pragma unroll
            for (int half = 0; half < 2; half++) {
                int row = bm + wm + mti * 16 + r0 + half * 8;
#pragma unroll
                for (int nt = 0; nt < 12; nt++) {
                    int cl = wn + nt * 8 + c0;
                    __half2 hv = *reinterpret_cast<__half2*>(&acc[mti][nt][half]);
                    float2 f = __half22float2(hv);
                    float v0 = f.x + bv[nt][0];
                    float v1 = f.y + bv[nt][1];
                    if (MODE == 0) {
                        if (!first) { v0 = fast_silu(v0); v1 = fast_silu(v1); }
                        __half* dst = first ? Y1 : Y2;
                        *(__half2*)&dst[(size_t)row * Cdim + cl] = packh2(v0, v1);
                    } else if (MODE == 1) {
                        v0 = fast_elu1(v0); v1 = fast_elu1(v1);
                        *(__half2*)&Y1[(size_t)row * N + bn + cl] = packh2(v0, v1);
                    } else {
                        float2 rr = *(const float2*)&resid[(size_t)row * N + bn + cl];
                        float2 o; o.x = v0 + rr.x; o.y = v1 + rr.y;
                        *(float2*)&Yf[(size_t)row * N + bn + cl] = o;
                    }
                }
            }
        }
    }
}

// ---------------------------------------------------------------------------
// Depthwise 3x3 + silu, half2 hfma2 arithmetic (96 threads, 2ch each, 4 rows)
// ---------------------------------------------------------------------------
__global__ void dwconv_silu_kernel(const __half2* __restrict__ in,
                                   const float* __restrict__ w,
                                   const float* __restrict__ bias,
                                   __half2* __restrict__ out)
{
    int blk = blockIdx.x;
    int c2  = threadIdx.x;
    int x   = blk % Wimg;
    int t   = blk / Wimg;
    int y4  = t % (Himg / 4);
    int b   = t / (Himg / 4);
    int y0  = y4 * 4;

    __half2 wv[9];
#pragma unroll
    for (int i = 0; i < 9; i++) {
        float2 wf = *(const float2*)&w[i * Cdim + 2 * c2];
        wv[i] = packh2(wf.x, wf.y);
    }
    float2 bf = *(const float2*)&bias[2 * c2];
    __half2 bb = packh2(bf.x, bf.y);
    __half2 acc[4];
#pragma unroll
    for (int i = 0; i < 4; i++) acc[i] = bb;

#pragma unroll
    for (int dx = 0; dx < 3; dx++) {
        int xx = x + dx - 1;
        if (xx < 0 || xx >= Wimg) continue;
#pragma unroll
        for (int ry = -1; ry < 5; ry++) {
            int yy = y0 + ry;
            if (yy < 0 || yy >= Himg) continue;
            __half2 v = in[((size_t)(b * Himg + yy) * Wimg + xx) * 96 + c2];
#pragma unroll
            for (int oy = 0; oy < 4; oy++) {
                int dy = ry - oy + 1;
                if (dy >= 0 && dy < 3)
                    acc[oy] = __hfma2(v, wv[dy * 3 + dx], acc[oy]);
            }
        }
    }
#pragma unroll
    for (int oy = 0; oy < 4; oy++) {
        float2 a = __half22float2(acc[oy]);
        out[((size_t)(b * Himg + y0 + oy) * Wimg + x) * 96 + c2] =
            packh2(fast_silu(a.x), fast_silu(a.y));
    }
}

// Fused: g = (att + dwconv(h)+lepe_b) * act_res, half2 arithmetic
__global__ void lepe_mul_kernel(const __half2* __restrict__ hin,
                                const float* __restrict__ w,
                                const float* __restrict__ bias,
                                const __half2* __restrict__ att,
                                const __half2* __restrict__ actres,
                                __half2* __restrict__ out)
{
    int blk = blockIdx.x;
    int c2  = threadIdx.x;
    int x   = blk % Wimg;
    int t   = blk / Wimg;
    int y4  = t % (Himg / 4);
    int b   = t / (Himg / 4);
    int y0  = y4 * 4;

    __half2 wv[9];
#pragma unroll
    for (int i = 0; i < 9; i++) {
        float2 wf = *(const float2*)&w[i * Cdim + 2 * c2];
        wv[i] = packh2(wf.x, wf.y);
    }
    float2 bf = *(const float2*)&bias[2 * c2];
    __half2 bb = packh2(bf.x, bf.y);
    __half2 acc[4];
#pragma unroll
    for (int i = 0; i < 4; i++) acc[i] = bb;

#pragma unroll
    for (int dx = 0; dx < 3; dx++) {
        int xx = x + dx - 1;
        if (xx < 0 || xx >= Wimg) continue;
#pragma unroll
        for (int ry = -1; ry < 5; ry++) {
            int yy = y0 + ry;
            if (yy < 0 || yy >= Himg) continue;
            __half2 v = hin[((size_t)(b * Himg + yy) * Wimg + xx) * 96 + c2];
#pragma unroll
            for (int oy = 0; oy < 4; oy++) {
                int dy = ry - oy + 1;
                if (dy >= 0 && dy < 3)
                    acc[oy] = __hfma2(v, wv[dy * 3 + dx], acc[oy]);
            }
        }
    }
#pragma unroll
    for (int oy = 0; oy < 4; oy++) {
        size_t pix = (size_t)(b * Himg + y0 + oy) * Wimg + x;
        __half2 at = att[pix * 96 + c2];
        __half2 ar = actres[pix * 96 + c2];
        out[pix * 96 + c2] = __hmul2(__hadd2(at, acc[oy]), ar);
    }
}

// ---------------------------------------------------------------------------
// kv: 4-way split over L, partials atomically accumulated.
// ---------------------------------------------------------------------------
__global__ void kv_kernel(const __half* __restrict__ qk,
                          const __half* __restrict__ hv,
                          float* __restrict__ kv, float* __restrict__ km)
{
    int bh = blockIdx.x;
    int b = bh / NHEAD, hd = bh % NHEAD;
    __shared__ float skv[HDIM * HDIM];
    __shared__ float skm[HDIM];
    int tid = threadIdx.x;
    for (int i = tid; i < HDIM * HDIM; i += blockDim.x) skv[i] = 0.f;
    if (tid < HDIM) skm[tid] = 0.f;
    __syncthreads();

    int lane = tid & 31, warp = tid >> 5;
    const int per = Lseq / KVSPLIT;
    int n0 = blockIdx.y * per;

    float acc[HDIM];
#pragma unroll
    for (int e = 0; e < HDIM; e++) acc[e] = 0.f;
    float acck = 0.f;

    for (int n = n0 + warp; n < n0 + per; n += 8) {
        size_t rowq = (size_t)(b * Lseq + n) * (2 * Cdim);
        float kd = __half2float(qk[rowq + Cdim + hd * HDIM + lane]);
        float ve = __half2float(hv[(size_t)(b * Lseq + n) * Cdim + hd * HDIM + lane]);
        acck += kd;
#pragma unroll
        for (int e = 0; e < HDIM; e++)
            acc[e] = fmaf(kd, __shfl_sync(0xffffffffu, ve, e), acc[e]);
    }
#pragma unroll
    for (int e = 0; e < HDIM; e++) atomicAdd(&skv[lane * HDIM + e], acc[e]);
    atomicAdd(&skm[lane], acck);
    __syncthreads();

    const float invL = 1.f / (float)Lseq;
    for (int i = tid; i < HDIM * HDIM; i += blockDim.x)
        atomicAdd(&kv[(size_t)bh * HDIM * HDIM + i], skv[i] * invL);
    if (tid < HDIM) atomicAdd(&km[bh * HDIM + tid], skm[tid] * invL);
}

// ---------------------------------------------------------------------------
__global__ void att_kernel(const __half* __restrict__ qk,
                           const float* __restrict__ kv,
                           const float* __restrict__ km, __half* __restrict__ att)
{
    int bh = blockIdx.x;
    int b = bh / NHEAD, hd = bh % NHEAD;
    __shared__ float skv[HDIM * HDIM];
    __shared__ float skm[HDIM];
    int tid = threadIdx.x;
    for (int i = tid; i < HDIM * HDIM; i += blockDim.x)
        skv[i] = kv[(size_t)bh * HDIM * HDIM + i];
    if (tid < HDIM) skm[tid] = km[bh * HDIM + tid];
    __syncthreads();

    int lane = tid & 31, warp = tid >> 5;
    const int per = Lseq / 8;
    int n0 = blockIdx.y * per;
    for (int n = n0 + warp; n < n0 + per; n += 8) {
        float qe = __half2float(qk[(size_t)(b * Lseq + n) * (2 * Cdim) + hd * HDIM + lane]);
        float p = qe * skm[lane];
#pragma unroll
        for (int o = 16; o > 0; o >>= 1) p += __shfl_xor_sync(0xffffffffu, p, o);
        float z = __fdividef(1.f, p + 1e-6f);
        float a = 0.f;
#pragma unroll
        for (int d = 0; d < HDIM; d++)
            a = fmaf(__shfl_sync(0xffffffffu, qe, d), skv[d * HDIM + lane], a);
        att[(size_t)(b * Lseq + n) * Cdim + hd * HDIM + lane] = __float2half(a * z);
    }
}

// ---------------------------------------------------------------------------
extern "C" void kernel_launch(void* const* d_in, const int* in_sizes, int n_in,
                              void* d_out, int out_size)
{
    const float* x      = (const float*)d_in[0];
    const float* norm_g = (const float*)d_in[1];
    const float* norm_b = (const float*)d_in[2];
    const float* in_w   = (const float*)d_in[3];
    const float* in_b   = (const float*)d_in[4];
    const float* act_w  = (const float*)d_in[5];
    const float* act_b  = (const float*)d_in[6];
    const float* dwc_w  = (const float*)d_in[7];
    const float* dwc_b  = (const float*)d_in[8];
    const float* qk_w   = (const float*)d_in[9];
    const float* qk_b   = (const float*)d_in[10];
    const float* lepe_w = (const float*)d_in[11];
    const float* lepe_b = (const float*)d_in[12];
    const float* out_w  = (const float*)d_in[13];
    const float* out_b  = (const float*)d_in[14];
    float* out = (float*)d_out;

    __half *xnh, *h0h, *acth, *hh, *qkh, *gh, *atth, *wcat, *qkw, *outw;
    float *kv, *km;
    cudaGetSymbolAddress((void**)&xnh,  g_xnh);
    cudaGetSymbolAddress((void**)&h0h,  g_h0h);
    cudaGetSymbolAddress((void**)&acth, g_acth);
    cudaGetSymbolAddress((void**)&hh,   g_hh);
    cudaGetSymbolAddress((void**)&qkh,  g_qkh);
    cudaGetSymbolAddress((void**)&gh,   g_gh);
    cudaGetSymbolAddress((void**)&atth, g_atth);
    cudaGetSymbolAddress((void**)&kv,   g_kv);
    cudaGetSymbolAddress((void**)&km,   g_km);
    cudaGetSymbolAddress((void**)&wcat, g_wcat);
    cudaGetSymbolAddress((void**)&qkw,  g_qkw);
    cudaGetSymbolAddress((void**)&outw, g_outw);

    cudaFuncSetAttribute(gemm_h<0>, cudaFuncAttributeMaxDynamicSharedMemorySize, SMEMP);
    cudaFuncSetAttribute(gemm_h<1>, cudaFuncAttributeMaxDynamicSharedMemorySize, SMEMP);
    cudaFuncSetAttribute(gemm_h<2>, cudaFuncAttributeMaxDynamicSharedMemorySize, SMEMP);

    // 0) weights -> fp16 + zero kv/km accumulators
    convw_kernel<<<(Cdim * 2 * Cdim + 255) / 256, 256>>>(in_w, act_w, qk_w, out_w);

    // 1) LayerNorm -> fp16
    ln_kernel<<<BL / 8, 256>>>(x, norm_g, norm_b, xnh);

    const int MT = BL / 128;   // 392

    // 2) fused in-proj + act-proj (N=384) — 2 CTAs/SM
    gemm_h<0><<<dim3(2, 148), 256, SMEMP>>>(
        xnh, wcat, in_b, act_b, nullptr, h0h, acth, nullptr, 2 * Cdim, MT);

    // 3) dwconv + silu -> h (half2 arithmetic)
    int dwgrid = BATCH * (Himg / 4) * Wimg;
    dwconv_silu_kernel<<<dwgrid, 96>>>((const __half2*)h0h, dwc_w, dwc_b,
                                       (__half2*)hh);

    // 4) qk-proj with elu+1 (N=384) — 2 CTAs/SM
    gemm_h<1><<<dim3(2, 148), 256, SMEMP>>>(
        hh, qkw, qk_b, nullptr, nullptr, qkh, nullptr, nullptr, 2 * Cdim, MT);

    // 5) linear attention (split-4 kv + fp16 att)
    kv_kernel<<<dim3(BATCH * NHEAD, KVSPLIT), 256>>>(qkh, hh, kv, km);
    att_kernel<<<dim3(BATCH * NHEAD, 8), 256>>>(qkh, kv, km, atth);

    // 6) g = (att + lepe) * act_res -> gh (half2 arithmetic)
    lepe_mul_kernel<<<dwgrid, 96>>>((const __half2*)hh, lepe_w, lepe_b,
                                    (const __half2*)atth,
                                    (const __half2*)acth, (__half2*)gh);

    // 7) out-proj + bias + shortcut -> fp32 out — 2 CTAs/SM
    gemm_h<2><<<dim3(1, 296), 256, SMEMP>>>(
        gh, outw, out_b, nullptr, x, nullptr, nullptr, out, Cdim, MT);
}

// round 17
// speedup vs baseline: 1.1115x; 1.0279x over previous
#include <cuda_runtime.h>
#include <cuda_fp16.h>
#include <stdint.h>
#include <math.h>

// ---------------------------------------------------------------------------
// EMLLA block, fp16. R16 structure (320.2us): persistent mma.sync GEMMs at
// 2 CTAs/SM (~67 TF/s = established ceiling), half2 convs, split kv, fp16 att.
// This round: att grid 8->14, kv split 4->6 (wave-packing micro-opts only).
// ---------------------------------------------------------------------------

constexpr int Himg = 56, Wimg = 56, Lseq = 3136, Cdim = 192;
constexpr int NHEAD = 6, HDIM = 32, BATCH = 16;
constexpr int BL = BATCH * Lseq;
constexpr float LN_EPS = 1e-5f;
constexpr int GK = 192;
constexpr int KVSPLIT = 6;
constexpr int ATTSPLIT = 14;

// Scratch (device globals: allocation-free, graph-capture safe)
__device__ __align__(16) __half g_xnh [(size_t)BL * Cdim];
__device__ __align__(16) __half g_h0h [(size_t)BL * Cdim];
__device__ __align__(16) __half g_acth[(size_t)BL * Cdim];
__device__ __align__(16) __half g_hh  [(size_t)BL * Cdim];
__device__ __align__(16) __half g_qkh [(size_t)BL * 2 * Cdim];
__device__ __align__(16) __half g_gh  [(size_t)BL * Cdim];
__device__ __align__(16) __half g_atth[(size_t)BL * Cdim];
__device__ __align__(16) float  g_kv  [BATCH * NHEAD * HDIM * HDIM];
__device__ __align__(16) float  g_km  [BATCH * NHEAD * HDIM];
__device__ __align__(16) __half g_wcat[Cdim * 2 * Cdim];   // [K,N] in_w|act_w
__device__ __align__(16) __half g_qkw [Cdim * 2 * Cdim];
__device__ __align__(16) __half g_outw[Cdim * Cdim];

// ---------------------------------------------------------------------------
__device__ __forceinline__ uint32_t smem_u32(const void* p) {
    return (uint32_t)__cvta_generic_to_shared(p);
}
__device__ __forceinline__ void ldm_x4(uint32_t& r0, uint32_t& r1, uint32_t& r2,
                                       uint32_t& r3, uint32_t a) {
    asm volatile("ldmatrix.sync.aligned.m8n8.x4.shared.b16 {%0,%1,%2,%3}, [%4];"
                 : "=r"(r0), "=r"(r1), "=r"(r2), "=r"(r3) : "r"(a));
}
__device__ __forceinline__ void ldm_x4t(uint32_t& r0, uint32_t& r1, uint32_t& r2,
                                        uint32_t& r3, uint32_t a) {
    asm volatile("ldmatrix.sync.aligned.m8n8.x4.trans.shared.b16 {%0,%1,%2,%3}, [%4];"
                 : "=r"(r0), "=r"(r1), "=r"(r2), "=r"(r3) : "r"(a));
}
__device__ __forceinline__ void mma_f16acc(uint32_t* c, uint32_t a0, uint32_t a1,
                                           uint32_t a2, uint32_t a3,
                                           uint32_t b0, uint32_t b1) {
    asm volatile(
        "mma.sync.aligned.m16n8k16.row.col.f16.f16.f16.f16 "
        "{%0,%1}, {%2,%3,%4,%5}, {%6,%7}, {%0,%1};"
        : "+r"(c[0]), "+r"(c[1])
        : "r"(a0), "r"(a1), "r"(a2), "r"(a3), "r"(b0), "r"(b1));
}
__device__ __forceinline__ void cpa16(uint32_t dst, const void* src) {
    asm volatile("cp.async.cg.shared.global [%0], [%1], 16;" :: "r"(dst), "l"(src));
}
__device__ __forceinline__ void cpa_commit() {
    asm volatile("cp.async.commit_group;" ::: "memory");
}
__device__ __forceinline__ void cpa_wait1() {
    asm volatile("cp.async.wait_group 1;" ::: "memory");
}
__device__ __forceinline__ void cpa_wait0() {
    asm volatile("cp.async.wait_group 0;" ::: "memory");
}
__device__ __forceinline__ __half2 packh2(float a, float b) {
    return __floats2half2_rn(a, b);
}
__device__ __forceinline__ float fast_silu(float v) {
    return __fdividef(v, 1.f + __expf(-v));
}
__device__ __forceinline__ float fast_elu1(float v) {
    return (v > 0.f) ? v + 1.f : __expf(v);
}

// ---------------------------------------------------------------------------
__global__ void convw_kernel(const float* __restrict__ in_w, const float* __restrict__ act_w,
                             const float* __restrict__ qk_w, const float* __restrict__ out_w)
{
    int i = blockIdx.x * 256 + threadIdx.x;
    if (i < Cdim * 2 * Cdim) {
        int r = i / (2 * Cdim), c = i % (2 * Cdim);
        float v = (c < Cdim) ? in_w[r * Cdim + c] : act_w[r * Cdim + (c - Cdim)];
        g_wcat[i] = __float2half(v);
        g_qkw[i]  = __float2half(qk_w[i]);
    }
    if (i < Cdim * Cdim) g_outw[i] = __float2half(out_w[i]);
    if (i < BATCH * NHEAD * HDIM * HDIM) g_kv[i] = 0.f;
    if (i < BATCH * NHEAD * HDIM) g_km[i] = 0.f;
}

// ---------------------------------------------------------------------------
__global__ void ln_kernel(const float* __restrict__ x, const float* __restrict__ gamma,
                          const float* __restrict__ beta, __half* __restrict__ out) {
    int row  = blockIdx.x * 8 + (threadIdx.x >> 5);
    int lane = threadIdx.x & 31;
    const float* xr = x + (size_t)row * Cdim;
    float v[6]; float s = 0.f, ss = 0.f;
#pragma unroll
    for (int i = 0; i < 6; i++) { v[i] = xr[lane + 32 * i]; s += v[i]; ss += v[i] * v[i]; }
#pragma unroll
    for (int o = 16; o > 0; o >>= 1) {
        s  += __shfl_xor_sync(0xffffffffu, s,  o);
        ss += __shfl_xor_sync(0xffffffffu, ss, o);
    }
    float mu   = s * (1.f / Cdim);
    float var  = ss * (1.f / Cdim) - mu * mu;
    float rstd = rsqrtf(var + LN_EPS);
    __half* orow = out + (size_t)row * Cdim;
#pragma unroll
    for (int i = 0; i < 6; i++) {
        int c = lane + 32 * i;
        orow[c] = __float2half((v[i] - mu) * rstd * gamma[c] + beta[c]);
    }
}

// ---------------------------------------------------------------------------
// Persistent weight-resident fp16 GEMM (f16 accumulate). 2 CTAs/SM.
// ---------------------------------------------------------------------------
constexpr int ASTR = 40, BSTR = 200;
constexpr int ASTAGE_B = 128 * ASTR * 2;
constexpr int BRES_B   = GK * BSTR * 2;
constexpr int SMEMP    = BRES_B + 2 * ASTAGE_B;   // 97280 (x2 = 194.5KB < 228KB)

template <int MODE>
__global__ __launch_bounds__(256) void gemm_h(
    const __half* __restrict__ A, const __half* __restrict__ W,
    const float* __restrict__ bias1, const float* __restrict__ bias2,
    const float* __restrict__ resid,
    __half* __restrict__ Y1, __half* __restrict__ Y2,
    float* __restrict__ Yf, int N, int mtiles)
{
    extern __shared__ __align__(16) char smem[];
    uint32_t bs_base = smem_u32(smem);
    uint32_t as_base = bs_base + BRES_B;

    int tid  = threadIdx.x;
    int bn   = blockIdx.x * 192;
    int warp = tid >> 5, lane = tid & 31;
    int wm   = (warp & 3) * 32, wn = (warp >> 2) * 96;

#pragma unroll
    for (int i = 0; i < 18; i++) {
        int idx = i * 256 + tid;
        int r = idx / 24, c = idx % 24;
        cpa16(bs_base + (r * BSTR + c * 8) * 2, W + (size_t)r * N + bn + c * 8);
    }
    cpa_commit();

    auto load_a = [&](int stage, int bm, int kt) {
        uint32_t ab = as_base + stage * ASTAGE_B;
#pragma unroll
        for (int i = 0; i < 2; i++) {
            int idx = i * 256 + tid;
            int r = idx >> 2, c = idx & 3;
            cpa16(ab + (r * ASTR + c * 8) * 2,
                  A + (size_t)(bm + r) * GK + kt * 32 + c * 8);
        }
        cpa_commit();
    };

    int a_row = wm + (lane & 7) + ((lane >> 3) & 1) * 8;
    int a_col = (lane >> 4) * 8;
    int b_k   = (lane & 7) + ((lane >> 3) & 1) * 8;
    int b_n   = wn + (lane >> 4) * 8;
    int r0 = lane >> 2, c0 = (lane & 3) * 2;
    bool first = (blockIdx.x == 0);

    float bv[12][2];
    {
        const float* bsrc = (MODE == 0) ? (first ? bias1 : bias2) : bias1;
#pragma unroll
        for (int nt = 0; nt < 12; nt++) {
            int cl = wn + nt * 8 + c0;
            int bi = (MODE == 0) ? cl : bn + cl;
            bv[nt][0] = bsrc[bi];
            bv[nt][1] = bsrc[bi + 1];
        }
    }

    int mt = blockIdx.y;
    if (mt < mtiles) load_a(0, mt * 128, 0);

    for (; mt < mtiles; mt += gridDim.y) {
        int bm = mt * 128;
        int next_mt = mt + gridDim.y;

        uint32_t acc[2][12][2];
#pragma unroll
        for (int i = 0; i < 2; i++)
#pragma unroll
            for (int j = 0; j < 12; j++) { acc[i][j][0] = 0u; acc[i][j][1] = 0u; }

#pragma unroll
        for (int kt = 0; kt < 6; kt++) {
            bool has_next = (kt < 5) || (next_mt < mtiles);
            if (has_next) {
                if (kt < 5) load_a((kt + 1) & 1, bm, kt + 1);
                else        load_a(0, next_mt * 128, 0);
                cpa_wait1();
            } else {
                cpa_wait0();
            }
            __syncthreads();
            uint32_t ab = as_base + (kt & 1) * ASTAGE_B;
#pragma unroll
            for (int ks = 0; ks < 2; ks++) {
                uint32_t afr[2][4];
#pragma unroll
                for (int mti = 0; mti < 2; mti++) {
                    uint32_t addr = ab + ((a_row + mti * 16) * ASTR + a_col + ks * 16) * 2;
                    ldm_x4(afr[mti][0], afr[mti][1], afr[mti][2], afr[mti][3], addr);
                }
                uint32_t bfr[12][2];
#pragma unroll
                for (int p = 0; p < 6; p++) {
                    uint32_t addr = bs_base +
                        ((kt * 32 + ks * 16 + b_k) * BSTR + b_n + p * 16) * 2;
                    uint32_t t0, t1, t2, t3;
                    ldm_x4t(t0, t1, t2, t3, addr);
                    bfr[p * 2 + 0][0] = t0; bfr[p * 2 + 0][1] = t1;
                    bfr[p * 2 + 1][0] = t2; bfr[p * 2 + 1][1] = t3;
                }
#pragma unroll
                for (int mti = 0; mti < 2; mti++)
#pragma unroll
                    for (int nt = 0; nt < 12; nt++)
                        mma_f16acc(acc[mti][nt], afr[mti][0], afr[mti][1],
                                   afr[mti][2], afr[mti][3], bfr[nt][0], bfr[nt][1]);
            }
            __syncthreads();
        }

#pragma unroll
        for (int mti = 0; mti < 2; mti++) {
#pragma unroll
            for (int half = 0; half < 2; half++) {
                int row = bm + wm + mti * 16 + r0 + half * 8;
#pragma unroll
                for (int nt = 0; nt < 12; nt++) {
                    int cl = wn + nt * 8 + c0;
                    __half2 hv = *reinterpret_cast<__half2*>(&acc[mti][nt][half]);
                    float2 f = __half22float2(hv);
                    float v0 = f.x + bv[nt][0];
                    float v1 = f.y + bv[nt][1];
                    if (MODE == 0) {
                        if (!first) { v0 = fast_silu(v0); v1 = fast_silu(v1); }
                        __half* dst = first ? Y1 : Y2;
                        *(__half2*)&dst[(size_t)row * Cdim + cl] = packh2(v0, v1);
                    } else if (MODE == 1) {
                        v0 = fast_elu1(v0); v1 = fast_elu1(v1);
                        *(__half2*)&Y1[(size_t)row * N + bn + cl] = packh2(v0, v1);
                    } else {
                        float2 rr = *(const float2*)&resid[(size_t)row * N + bn + cl];
                        float2 o; o.x = v0 + rr.x; o.y = v1 + rr.y;
                        *(float2*)&Yf[(size_t)row * N + bn + cl] = o;
                    }
                }
            }
        }
    }
}

// ---------------------------------------------------------------------------
// Depthwise 3x3 + silu, half2 hfma2 arithmetic (96 threads, 2ch each, 4 rows)
// ---------------------------------------------------------------------------
__global__ void dwconv_silu_kernel(const __half2* __restrict__ in,
                                   const float* __restrict__ w,
                                   const float* __restrict__ bias,
                                   __half2* __restrict__ out)
{
    int blk = blockIdx.x;
    int c2  = threadIdx.x;
    int x   = blk % Wimg;
    int t   = blk / Wimg;
    int y4  = t % (Himg / 4);
    int b   = t / (Himg / 4);
    int y0  = y4 * 4;

    __half2 wv[9];
#pragma unroll
    for (int i = 0; i < 9; i++) {
        float2 wf = *(const float2*)&w[i * Cdim + 2 * c2];
        wv[i] = packh2(wf.x, wf.y);
    }
    float2 bf = *(const float2*)&bias[2 * c2];
    __half2 bb = packh2(bf.x, bf.y);
    __half2 acc[4];
#pragma unroll
    for (int i = 0; i < 4; i++) acc[i] = bb;

#pragma unroll
    for (int dx = 0; dx < 3; dx++) {
        int xx = x + dx - 1;
        if (xx < 0 || xx >= Wimg) continue;
#pragma unroll
        for (int ry = -1; ry < 5; ry++) {
            int yy = y0 + ry;
            if (yy < 0 || yy >= Himg) continue;
            __half2 v = in[((size_t)(b * Himg + yy) * Wimg + xx) * 96 + c2];
#pragma unroll
            for (int oy = 0; oy < 4; oy++) {
                int dy = ry - oy + 1;
                if (dy >= 0 && dy < 3)
                    acc[oy] = __hfma2(v, wv[dy * 3 + dx], acc[oy]);
            }
        }
    }
#pragma unroll
    for (int oy = 0; oy < 4; oy++) {
        float2 a = __half22float2(acc[oy]);
        out[((size_t)(b * Himg + y0 + oy) * Wimg + x) * 96 + c2] =
            packh2(fast_silu(a.x), fast_silu(a.y));
    }
}

// Fused: g = (att + dwconv(h)+lepe_b) * act_res, half2 arithmetic
__global__ void lepe_mul_kernel(const __half2* __restrict__ hin,
                                const float* __restrict__ w,
                                const float* __restrict__ bias,
                                const __half2* __restrict__ att,
                                const __half2* __restrict__ actres,
                                __half2* __restrict__ out)
{
    int blk = blockIdx.x;
    int c2  = threadIdx.x;
    int x   = blk % Wimg;
    int t   = blk / Wimg;
    int y4  = t % (Himg / 4);
    int b   = t / (Himg / 4);
    int y0  = y4 * 4;

    __half2 wv[9];
#pragma unroll
    for (int i = 0; i < 9; i++) {
        float2 wf = *(const float2*)&w[i * Cdim + 2 * c2];
        wv[i] = packh2(wf.x, wf.y);
    }
    float2 bf = *(const float2*)&bias[2 * c2];
    __half2 bb = packh2(bf.x, bf.y);
    __half2 acc[4];
#pragma unroll
    for (int i = 0; i < 4; i++) acc[i] = bb;

#pragma unroll
    for (int dx = 0; dx < 3; dx++) {
        int xx = x + dx - 1;
        if (xx < 0 || xx >= Wimg) continue;
#pragma unroll
        for (int ry = -1; ry < 5; ry++) {
            int yy = y0 + ry;
            if (yy < 0 || yy >= Himg) continue;
            __half2 v = hin[((size_t)(b * Himg + yy) * Wimg + xx) * 96 + c2];
#pragma unroll
            for (int oy = 0; oy < 4; oy++) {
                int dy = ry - oy + 1;
                if (dy >= 0 && dy < 3)
                    acc[oy] = __hfma2(v, wv[dy * 3 + dx], acc[oy]);
            }
        }
    }
#pragma unroll
    for (int oy = 0; oy < 4; oy++) {
        size_t pix = (size_t)(b * Himg + y0 + oy) * Wimg + x;
        __half2 at = att[pix * 96 + c2];
        __half2 ar = actres[pix * 96 + c2];
        out[pix * 96 + c2] = __hmul2(__hadd2(at, acc[oy]), ar);
    }
}

// ---------------------------------------------------------------------------
// kv: 6-way split over L, partials atomically accumulated.
// Lseq = 3136 is not divisible by 6 -> use ceil-division bounds.
// ---------------------------------------------------------------------------
__global__ void kv_kernel(const __half* __restrict__ qk,
                          const __half* __restrict__ hv,
                          float* __restrict__ kv, float* __restrict__ km)
{
    int bh = blockIdx.x;
    int b = bh / NHEAD, hd = bh % NHEAD;
    __shared__ float skv[HDIM * HDIM];
    __shared__ float skm[HDIM];
    int tid = threadIdx.x;
    for (int i = tid; i < HDIM * HDIM; i += blockDim.x) skv[i] = 0.f;
    if (tid < HDIM) skm[tid] = 0.f;
    __syncthreads();

    int lane = tid & 31, warp = tid >> 5;
    const int per = (Lseq + KVSPLIT - 1) / KVSPLIT;   // 523
    int n0 = blockIdx.y * per;
    int n1 = min(n0 + per, Lseq);

    float acc[HDIM];
#pragma unroll
    for (int e = 0; e < HDIM; e++) acc[e] = 0.f;
    float acck = 0.f;

    for (int n = n0 + warp; n < n1; n += 8) {
        size_t rowq = (size_t)(b * Lseq + n) * (2 * Cdim);
        float kd = __half2float(qk[rowq + Cdim + hd * HDIM + lane]);
        float ve = __half2float(hv[(size_t)(b * Lseq + n) * Cdim + hd * HDIM + lane]);
        acck += kd;
#pragma unroll
        for (int e = 0; e < HDIM; e++)
            acc[e] = fmaf(kd, __shfl_sync(0xffffffffu, ve, e), acc[e]);
    }
#pragma unroll
    for (int e = 0; e < HDIM; e++) atomicAdd(&skv[lane * HDIM + e], acc[e]);
    atomicAdd(&skm[lane], acck);
    __syncthreads();

    const float invL = 1.f / (float)Lseq;
    for (int i = tid; i < HDIM * HDIM; i += blockDim.x)
        atomicAdd(&kv[(size_t)bh * HDIM * HDIM + i], skv[i] * invL);
    if (tid < HDIM) atomicAdd(&km[bh * HDIM + tid], skm[tid] * invL);
}

// ---------------------------------------------------------------------------
// att -> fp16. grid.y = ATTSPLIT (Lseq = 3136 = 14 * 224).
// ---------------------------------------------------------------------------
__global__ void att_kernel(const __half* __restrict__ qk,
                           const float* __restrict__ kv,
                           const float* __restrict__ km, __half* __restrict__ att)
{
    int bh = blockIdx.x;
    int b = bh / NHEAD, hd = bh % NHEAD;
    __shared__ float skv[HDIM * HDIM];
    __shared__ float skm[HDIM];
    int tid = threadIdx.x;
    for (int i = tid; i < HDIM * HDIM; i += blockDim.x)
        skv[i] = kv[(size_t)bh * HDIM * HDIM + i];
    if (tid < HDIM) skm[tid] = km[bh * HDIM + tid];
    __syncthreads();

    int lane = tid & 31, warp = tid >> 5;
    const int per = Lseq / ATTSPLIT;                  // 224
    int n0 = blockIdx.y * per;
    for (int n = n0 + warp; n < n0 + per; n += 8) {
        float qe = __half2float(qk[(size_t)(b * Lseq + n) * (2 * Cdim) + hd * HDIM + lane]);
        float p = qe * skm[lane];
#pragma unroll
        for (int o = 16; o > 0; o >>= 1) p += __shfl_xor_sync(0xffffffffu, p, o);
        float z = __fdividef(1.f, p + 1e-6f);
        float a = 0.f;
#pragma unroll
        for (int d = 0; d < HDIM; d++)
            a = fmaf(__shfl_sync(0xffffffffu, qe, d), skv[d * HDIM + lane], a);
        att[(size_t)(b * Lseq + n) * Cdim + hd * HDIM + lane] = __float2half(a * z);
    }
}

// ---------------------------------------------------------------------------
extern "C" void kernel_launch(void* const* d_in, const int* in_sizes, int n_in,
                              void* d_out, int out_size)
{
    const float* x      = (const float*)d_in[0];
    const float* norm_g = (const float*)d_in[1];
    const float* norm_b = (const float*)d_in[2];
    const float* in_w   = (const float*)d_in[3];
    const float* in_b   = (const float*)d_in[4];
    const float* act_w  = (const float*)d_in[5];
    const float* act_b  = (const float*)d_in[6];
    const float* dwc_w  = (const float*)d_in[7];
    const float* dwc_b  = (const float*)d_in[8];
    const float* qk_w   = (const float*)d_in[9];
    const float* qk_b   = (const float*)d_in[10];
    const float* lepe_w = (const float*)d_in[11];
    const float* lepe_b = (const float*)d_in[12];
    const float* out_w  = (const float*)d_in[13];
    const float* out_b  = (const float*)d_in[14];
    float* out = (float*)d_out;

    __half *xnh, *h0h, *acth, *hh, *qkh, *gh, *atth, *wcat, *qkw, *outw;
    float *kv, *km;
    cudaGetSymbolAddress((void**)&xnh,  g_xnh);
    cudaGetSymbolAddress((void**)&h0h,  g_h0h);
    cudaGetSymbolAddress((void**)&acth, g_acth);
    cudaGetSymbolAddress((void**)&hh,   g_hh);
    cudaGetSymbolAddress((void**)&qkh,  g_qkh);
    cudaGetSymbolAddress((void**)&gh,   g_gh);
    cudaGetSymbolAddress((void**)&atth, g_atth);
    cudaGetSymbolAddress((void**)&kv,   g_kv);
    cudaGetSymbolAddress((void**)&km,   g_km);
    cudaGetSymbolAddress((void**)&wcat, g_wcat);
    cudaGetSymbolAddress((void**)&qkw,  g_qkw);
    cudaGetSymbolAddress((void**)&outw, g_outw);

    cudaFuncSetAttribute(gemm_h<0>, cudaFuncAttributeMaxDynamicSharedMemorySize, SMEMP);
    cudaFuncSetAttribute(gemm_h<1>, cudaFuncAttributeMaxDynamicSharedMemorySize, SMEMP);
    cudaFuncSetAttribute(gemm_h<2>, cudaFuncAttributeMaxDynamicSharedMemorySize, SMEMP);

    // 0) weights -> fp16 + zero kv/km accumulators
    convw_kernel<<<(Cdim * 2 * Cdim + 255) / 256, 256>>>(in_w, act_w, qk_w, out_w);

    // 1) LayerNorm -> fp16
    ln_kernel<<<BL / 8, 256>>>(x, norm_g, norm_b, xnh);

    const int MT = BL / 128;   // 392

    // 2) fused in-proj + act-proj (N=384) — 2 CTAs/SM
    gemm_h<0><<<dim3(2, 148), 256, SMEMP>>>(
        xnh, wcat, in_b, act_b, nullptr, h0h, acth, nullptr, 2 * Cdim, MT);

    // 3) dwconv + silu -> h (half2 arithmetic)
    int dwgrid = BATCH * (Himg / 4) * Wimg;
    dwconv_silu_kernel<<<dwgrid, 96>>>((const __half2*)h0h, dwc_w, dwc_b,
                                       (__half2*)hh);

    // 4) qk-proj with elu+1 (N=384) — 2 CTAs/SM
    gemm_h<1><<<dim3(2, 148), 256, SMEMP>>>(
        hh, qkw, qk_b, nullptr, nullptr, qkh, nullptr, nullptr, 2 * Cdim, MT);

    // 5) linear attention (split-6 kv + fp16 att, grid 14)
    kv_kernel<<<dim3(BATCH * NHEAD, KVSPLIT), 256>>>(qkh, hh, kv, km);
    att_kernel<<<dim3(BATCH * NHEAD, ATTSPLIT), 256>>>(qkh, kv, km, atth);

    // 6) g = (att + lepe) * act_res -> gh (half2 arithmetic)
    lepe_mul_kernel<<<dwgrid, 96>>>((const __half2*)hh, lepe_w, lepe_b,
                                    (const __half2*)atth,
                                    (const __half2*)acth, (__half2*)gh);

    // 7) out-proj + bias + shortcut -> fp32 out — 2 CTAs/SM
    gemm_h<2><<<dim3(1, 296), 256, SMEMP>>>(
        gh, outw, out_b, nullptr, x, nullptr, nullptr, out, Cdim, MT);
}